// round 17
// baseline (speedup 1.0000x reference)
#include <cuda_runtime.h>
#include <cuda_fp16.h>
#include <cstdint>
#include <math.h>

// Problem constants (fixed by the reference setup_inputs)
#define MPTS   4096
#define NBATCH 4
#define NITERS 50
#define NSLOTS 2            // batch slots fused into one barrier group
#define GB     148          // blocks = SMs; 1 block/SM at NT=1024
#define NT     1024
#define NW     32
#define CR     8            // rows per register-held chunk
#define TPAD   160          // partial rows padded to 32*5 (pads stay zero)
#define INV_N  (1.0f/4096.0f)
#define USCALE 16777216.0f  // 2^24 : u scaled into half-friendly range
#define VSCALE 4096.0f      // INV_N * 2^24 : folded into colfix division
#define SURV_THRESH 1e-5f

// Barrier counters: 0 = setup (blocking), 1..4 = A,B,C,D (split arrive/wait)
#define BAR_S 0
#define BAR_A 1
#define BAR_B 2
#define BAR_C 3
#define BAR_D 4

// Scratch (device globals; allocation-free per harness rules).
__device__ __half g_K16[NSLOTS][(size_t)MPTS * MPTS];   // 2 x 32 MB, L2-resident
__device__ float  g_u[NSLOTS][MPTS];
__device__ float  g_v[NSLOTS][MPTS];
__device__ float  g_T[NSLOTS][TPAD][MPTS];              // partials; rows 148..159 = 0
__device__ float  g_cmax[NSLOTS][GB];
__device__ float  g_loss[NBATCH][GB][3];                // cnt, velsq, bce
struct Bar { unsigned c; unsigned pad[31]; };           // 128B separation
__device__ Bar g_bar[5];

__device__ __forceinline__ float warpMax(float v){
    #pragma unroll
    for (int o = 16; o; o >>= 1) v = fmaxf(v, __shfl_xor_sync(0xffffffffu, v, o));
    return v;
}
__device__ __forceinline__ float warpSum(float v){
    #pragma unroll
    for (int o = 16; o; o >>= 1) v += __shfl_xor_sync(0xffffffffu, v, o);
    return v;
}
__device__ __forceinline__ float ex2(float x){
    float r; asm("ex2.approx.f32 %0, %1;" : "=f"(r) : "f"(x)); return r;
}

// Split grid barrier: arrive publishes this block's work; wait blocks until
// all GB blocks reached the given cumulative target.
__device__ __forceinline__ void garr(int b){
    __syncthreads();
    if (threadIdx.x == 0){ __threadfence(); atomicAdd(&g_bar[b].c, 1u); }
}
__device__ __forceinline__ void gwait(int b, unsigned tgt){
    if (threadIdx.x == 0){
        while (*((volatile unsigned*)&g_bar[b].c) < tgt) __nanosleep(32);
    }
    __syncthreads();
}

__shared__ float   s_red[CR][NT];       // row-sum partials (32 KB)
__shared__ __half2 s_su[CR];            // scaled u' per chunk row
__shared__ float   s_sr[NW];
__shared__ float   s_scalar;
__shared__ float   s_mx[NW];
__shared__ int     s_mi[NW];
__shared__ float   s_B[NW][33];         // colfix transpose buffer

// Rowpass for one slot: chunks of 8 rows held in registers (uint2/thread);
// pass B reuses the held registers -> K is read from L1/L2 ONCE.
__device__ void rowpass(const __half* __restrict__ Kh,
                        const float* __restrict__ vS,
                        float* __restrict__ uS,
                        float* __restrict__ Tp,
                        int rstart, int rend)
{
    int t = threadIdx.x, warp = t >> 5, lane = t & 31;
    const __half2 hz = __floats2half2_rn(0.f, 0.f);
    __half2 vh0, vh1;
    {
        float4 v0 = __ldcg((const float4*)(vS + 4*t));
        vh0 = __floats2half2_rn(v0.x, v0.y);
        vh1 = __floats2half2_rn(v0.z, v0.w);
    }
    float Tacc[4] = {0.f, 0.f, 0.f, 0.f};

    // 3 full chunks of 8 rows
    #pragma unroll 1
    for (int f = 0; f < 3; f++){
        int ib = rstart + f * CR;
        uint2 kr[CR];
        #pragma unroll
        for (int r = 0; r < CR; r++)
            kr[r] = ((const uint2*)(Kh + (size_t)(ib + r) * MPTS))[t];
        #pragma unroll
        for (int r = 0; r < CR; r++){
            const __half2* a2 = (const __half2*)&kr[r];
            __half2 acc = __hfma2(a2[0], vh0, hz);
            acc = __hfma2(a2[1], vh1, acc);
            float2 fv = __half22float2(acc);
            s_red[r][t] = fv.x + fv.y;
        }
        __syncthreads();
        if (warp < CR){
            float S = 0.f;
            #pragma unroll
            for (int q = 0; q < NW; q++) S += s_red[warp][lane + 32*q];
            S = warpSum(S);
            if (lane == 0){
                float u = INV_N / S;
                uS[ib + warp] = u;
                s_su[warp] = __float2half2_rn(u * USCALE);
            }
        }
        __syncthreads();
        __half2 Ts0 = hz, Ts1 = hz;
        #pragma unroll
        for (int r = 0; r < CR; r++){
            const __half2* a2 = (const __half2*)&kr[r];
            __half2 uh = s_su[r];
            Ts0 = __hfma2(a2[0], uh, Ts0);
            Ts1 = __hfma2(a2[1], uh, Ts1);
        }
        float2 f0 = __half22float2(Ts0), f1 = __half22float2(Ts1);
        Tacc[0] += f0.x; Tacc[1] += f0.y; Tacc[2] += f1.x; Tacc[3] += f1.y;
    }
    // tail: 3 or 4 rows
    {
        int ib = rstart + 24;
        int nr = rend - ib;
        uint2 kr[4];
        #pragma unroll
        for (int r = 0; r < 4; r++)
            if (r < nr) kr[r] = ((const uint2*)(Kh + (size_t)(ib + r) * MPTS))[t];
        #pragma unroll
        for (int r = 0; r < 4; r++){
            if (r < nr){
                const __half2* a2 = (const __half2*)&kr[r];
                __half2 acc = __hfma2(a2[0], vh0, hz);
                acc = __hfma2(a2[1], vh1, acc);
                float2 fv = __half22float2(acc);
                s_red[r][t] = fv.x + fv.y;
            }
        }
        __syncthreads();
        if (warp < nr){
            float S = 0.f;
            #pragma unroll
            for (int q = 0; q < NW; q++) S += s_red[warp][lane + 32*q];
            S = warpSum(S);
            if (lane == 0){
                float u = INV_N / S;
                uS[ib + warp] = u;
                s_su[warp] = __float2half2_rn(u * USCALE);
            }
        }
        __syncthreads();
        __half2 Ts0 = hz, Ts1 = hz;
        #pragma unroll
        for (int r = 0; r < 4; r++){
            if (r < nr){
                const __half2* a2 = (const __half2*)&kr[r];
                __half2 uh = s_su[r];
                Ts0 = __hfma2(a2[0], uh, Ts0);
                Ts1 = __hfma2(a2[1], uh, Ts1);
            }
        }
        float2 f0 = __half22float2(Ts0), f1 = __half22float2(Ts1);
        Tacc[0] += f0.x; Tacc[1] += f0.y; Tacc[2] += f1.x; Tacc[3] += f1.y;
    }
    ((float4*)Tp)[t] = make_float4(Tacc[0], Tacc[1], Tacc[2], Tacc[3]);
}

// Colfix for one slot: warp w sums partial rows [5w,5w+5) at column
// rstart+lane (coalesced), then a 32-way SMEM combine.
__device__ void colfix(const float (*Tslot)[MPTS], float* __restrict__ vS,
                       int rstart, int ncols)
{
    int t = threadIdx.x, warp = t >> 5, lane = t & 31;
    float s = 0.f;
    if (lane < ncols){
        int c = rstart + lane;
        #pragma unroll
        for (int p = 0; p < 5; p++) s += __ldcg(&Tslot[5*warp + p][c]);
    }
    s_B[warp][lane] = s;
    __syncthreads();
    if (t < 32 && lane < ncols){
        float T = 0.f;
        #pragma unroll
        for (int g = 0; g < NW; g++) T += s_B[g][lane];
        vS[rstart + lane] = VSCALE / T;
    }
}

// ---------------------------------------------------------------------------
// Persistent kernel: 148 blocks (1/SM, 1024 thr). Each block owns the same
// row range for BOTH batch slots; the two slots share one barrier group and
// are software-pipelined with split arrive/wait barriers so barrier latency
// hides under the other slot's work:
//   rowpass0 -> arrA -> rowpass1 -> arrB -> waitA -> colfix0 -> arrC
//   -> waitB -> colfix1 -> arrD ; next iter waits C/D before each rowpass.
// ---------------------------------------------------------------------------
__global__ void __launch_bounds__(NT, 1) k_persist(
        const float* __restrict__ x0p, const float* __restrict__ xgp,
        const float* __restrict__ vpp, const float* __restrict__ alp,
        int b0, int itbase, unsigned sbase)
{
    int t = threadIdx.x, warp = t >> 5, lane = t & 31;
    int blk = blockIdx.x;
    int rstart = (blk * MPTS) / GB;
    int rend   = ((blk + 1) * MPTS) / GB;   // 27 or 28 rows
    int ncols  = rend - rstart;

    // ---- Phase 0: block-local cost max for both slots --------------------
    #pragma unroll 1
    for (int s = 0; s < NSLOTS; s++){
        const float* x0 = x0p + (size_t)s * MPTS * 3;
        const float* xg = xgp + (size_t)s * MPTS * 3;
        float gx[4], gy[4], gz[4];
        {
            const float* bg = xg + 12 * t;
            #pragma unroll
            for (int c = 0; c < 4; c++){
                gx[c] = bg[3*c]; gy[c] = bg[3*c+1]; gz[c] = bg[3*c+2];
            }
        }
        float mx = 0.f;
        for (int i = rstart; i < rend; i++){
            float ax = x0[3*i], ay = x0[3*i+1], az = x0[3*i+2];
            #pragma unroll
            for (int c = 0; c < 4; c++){
                float dx = ax-gx[c], dy = ay-gy[c], dz = az-gz[c];
                mx = fmaxf(mx, dx*dx + dy*dy + dz*dz);
            }
        }
        mx = warpMax(mx);
        if (lane == 0) s_sr[warp] = mx;
        __syncthreads();
        if (t == 0){
            float m = s_sr[0];
            #pragma unroll
            for (int w = 1; w < NW; w++) m = fmaxf(m, s_sr[w]);
            g_cmax[s][blk] = m;
        }
        __syncthreads();
    }
    garr(BAR_S); gwait(BAR_S, sbase + GB);

    // ---- Phase 1: scale + K16 for both slots; init v ---------------------
    #pragma unroll 1
    for (int s = 0; s < NSLOTS; s++){
        const float* x0 = x0p + (size_t)s * MPTS * 3;
        const float* xg = xgp + (size_t)s * MPTS * 3;
        __half* Kh = g_K16[s];
        float mc = (t < GB) ? __ldcg(&g_cmax[s][t]) : 0.f;
        mc = warpMax(mc);
        if (lane == 0) s_sr[warp] = mc;
        __syncthreads();
        if (t == 0){
            float m = s_sr[0];
            #pragma unroll
            for (int w = 1; w < NW; w++) m = fmaxf(m, s_sr[w]);
            s_scalar = -1.44269504088896340736f / (0.1f * m);
        }
        __syncthreads();
        float scale = s_scalar;
        float gx[4], gy[4], gz[4];
        {
            const float* bg = xg + 12 * t;
            #pragma unroll
            for (int c = 0; c < 4; c++){
                gx[c] = bg[3*c]; gy[c] = bg[3*c+1]; gz[c] = bg[3*c+2];
            }
        }
        for (int i = rstart; i < rend; i++){
            float ax = x0[3*i], ay = x0[3*i+1], az = x0[3*i+2];
            __half2 hk[2];
            #pragma unroll
            for (int c = 0; c < 4; c += 2){
                float dx = ax-gx[c],   dy = ay-gy[c],   dz = az-gz[c];
                float e0 = ex2(fmaf(dx*dx + dy*dy + dz*dz, scale, 4.0f));
                dx = ax-gx[c+1]; dy = ay-gy[c+1]; dz = az-gz[c+1];
                float e1 = ex2(fmaf(dx*dx + dy*dy + dz*dz, scale, 4.0f));
                hk[c/2] = __floats2half2_rn(e0, e1);
            }
            ((uint2*)(Kh + (size_t)i * MPTS))[t] = *(uint2*)&hk[0];
        }
        if (blk == 0){
            #pragma unroll
            for (int q = 0; q < 4; q++) g_v[s][t + 1024*q] = 1.0f;
        }
        __syncthreads();
    }
    garr(BAR_S); gwait(BAR_S, sbase + 2*GB);

    // ---- Phase 2: 50 pipelined Sinkhorn iterations (both slots) ----------
    for (int it = 0; it < NITERS; it++){
        unsigned k = (unsigned)(itbase + it);
        gwait(BAR_C, k * GB);               // v0 of prev iter complete
        rowpass(g_K16[0], g_v[0], g_u[0], &g_T[0][blk][0], rstart, rend);
        garr(BAR_A);
        gwait(BAR_D, k * GB);               // v1 of prev iter complete
        rowpass(g_K16[1], g_v[1], g_u[1], &g_T[1][blk][0], rstart, rend);
        garr(BAR_B);
        gwait(BAR_A, (k + 1) * GB);         // all T0 published
        colfix(g_T[0], g_v[0], rstart, ncols);
        garr(BAR_C);
        gwait(BAR_B, (k + 1) * GB);         // all T1 published
        colfix(g_T[1], g_v[1], rstart, ncols);
        garr(BAR_D);
    }
    gwait(BAR_C, (unsigned)(itbase + NITERS) * GB);
    gwait(BAR_D, (unsigned)(itbase + NITERS) * GB);

    // ---- Phase 3: argmax of pi = u*K*v, survival, loss partials ----------
    #pragma unroll 1
    for (int s = 0; s < NSLOTS; s++){
        const float* x0 = x0p + (size_t)s * MPTS * 3;
        const float* xg = xgp + (size_t)s * MPTS * 3;
        const float* vp = vpp + (size_t)s * MPTS * 3;
        const float* al = alp + (size_t)s * MPTS;
        const __half* Kh = g_K16[s];
        float vr[4];
        {
            float4 v0 = __ldcg((const float4*)(g_v[s] + 4*t));
            vr[0]=v0.x; vr[1]=v0.y; vr[2]=v0.z; vr[3]=v0.w;
        }
        float cnt = 0.f, velsq = 0.f, bce = 0.f;   // thread 0 accumulates
        for (int i = rstart; i < rend; i++){
            uint2 ka = ((const uint2*)(Kh + (size_t)i * MPTS))[t];
            const __half2* a2 = (const __half2*)&ka;
            float m = -1.f; int mi = 0;
            #pragma unroll
            for (int q = 0; q < 2; q++){
                float2 f = __half22float2(a2[q]);
                float p0 = f.x * vr[2*q], p1 = f.y * vr[2*q+1];
                if (p0 > m){ m = p0; mi = 4*t + 2*q; }
                if (p1 > m){ m = p1; mi = 4*t + 2*q + 1; }
            }
            #pragma unroll
            for (int o = 16; o; o >>= 1){
                float om = __shfl_xor_sync(0xffffffffu, m, o);
                int   oi = __shfl_xor_sync(0xffffffffu, mi, o);
                if (om > m || (om == m && oi < mi)){ m = om; mi = oi; }
            }
            if (lane == 0){ s_mx[warp] = m; s_mi[warp] = mi; }
            __syncthreads();
            if (t == 0){
                #pragma unroll
                for (int w = 1; w < NW; w++){
                    if (s_mx[w] > m || (s_mx[w] == m && s_mi[w] < mi)){
                        m = s_mx[w]; mi = s_mi[w];
                    }
                }
                float p = g_u[s][i] * m;
                float a_i = al[i];
                float sp = fmaxf(a_i, 0.f) + log1pf(expf(-fabsf(a_i)));
                bce += sp;
                if (p > SURV_THRESH){
                    cnt += 1.f;
                    bce -= a_i;
                    #pragma unroll
                    for (int d = 0; d < 3; d++){
                        float vt = xg[3*mi + d] - x0[3*i + d];
                        float df = vp[3*i + d] - vt;
                        velsq = fmaf(df, df, velsq);
                    }
                }
            }
            __syncthreads();
        }
        if (t == 0){
            g_loss[b0 + s][blk][0] = cnt;
            g_loss[b0 + s][blk][1] = velsq;
            g_loss[b0 + s][blk][2] = bce;
        }
        __syncthreads();
    }
}

// ---------------------------------------------------------------------------
// Final reduction; also resets the barrier counters for the next replay.
__global__ void __launch_bounds__(256) k_loss(float* __restrict__ out){
    int t = threadIdx.x;
    if (t < 5) g_bar[t].c = 0u;
    float cnt = 0.f, velsq = 0.f, bce = 0.f;
    for (int idx = t; idx < NBATCH * GB; idx += 256){
        int b = idx / GB, p = idx % GB;
        cnt   += g_loss[b][p][0];
        velsq += g_loss[b][p][1];
        bce   += g_loss[b][p][2];
    }
    cnt = warpSum(cnt); velsq = warpSum(velsq); bce = warpSum(bce);
    __shared__ float sc[8], sv[8], sb2[8];
    if ((t & 31) == 0){ sc[t>>5] = cnt; sv[t>>5] = velsq; sb2[t>>5] = bce; }
    __syncthreads();
    if (t == 0){
        float C = 0.f, V = 0.f, Bc = 0.f;
        #pragma unroll
        for (int w = 0; w < 8; w++){ C += sc[w]; V += sv[w]; Bc += sb2[w]; }
        float denom = fmaxf(C, 1.f);
        out[0] = V / denom + Bc / (float)(NBATCH * MPTS);
    }
}

// ---------------------------------------------------------------------------
extern "C" void kernel_launch(void* const* d_in, const int* in_sizes, int n_in,
                              void* d_out, int out_size){
    const float* x0 = (const float*)d_in[0];   // (B, M, 3)
    const float* xg = (const float*)d_in[1];   // (B, K, 3)
    const float* vp = (const float*)d_in[2];   // (B, M, 3)
    const float* al = (const float*)d_in[3];   // (B, M, 1)
    (void)in_sizes; (void)n_in; (void)out_size;

    for (int l = 0; l < NBATCH / NSLOTS; l++){
        int b0 = l * NSLOTS;
        k_persist<<<GB, NT>>>(x0 + (size_t)b0 * MPTS * 3,
                              xg + (size_t)b0 * MPTS * 3,
                              vp + (size_t)b0 * MPTS * 3,
                              al + (size_t)b0 * MPTS,
                              b0, l * NITERS, (unsigned)(l * 2 * GB));
    }
    k_loss<<<1, 256>>>((float*)d_out);
}